// round 5
// baseline (speedup 1.0000x reference)
#include <cuda_runtime.h>

#define H 512
#define B 128
#define T 1024
#define NCLS 10

#define GRID 128
#define TPB 512
#define BT 32          // batch tile per block
#define JT 16          // hidden-column tile per block
#define GS 516         // padded smem stride per gate row (floats)
#define WJ (4*GS)      // per-j W block (4 gates)
#define HS 516         // padded smem row stride for h (floats)
#define REDF 2048      // reduction buffer floats (256 threads * 8)

#define SMEM_FLOATS (JT*WJ + BT*HS + REDF)   // 33024+16512+2048 = 51584
#define SMEM_BYTES  (SMEM_FLOATS * 4)        // 206336

typedef unsigned long long ull;

// ---------------- device scratch (static, no allocation) ----------------
__device__ float g_xT[T * B];            // transposed x
__device__ float g_h[2][B * H];          // ping-pong hidden state [b][k]
__device__ unsigned g_cnt4[4];
__device__ unsigned g_gen4[4];

// ---------------- helpers ----------------
__device__ __forceinline__ ull fma2(ull a, ull b, ull c) {
    ull d;
    asm("fma.rn.f32x2 %0, %1, %2, %3;" : "=l"(d) : "l"(a), "l"(b), "l"(c));
    return d;
}
__device__ __forceinline__ float hadd2(ull a) {
    union { ull u; float2 f; } x; x.u = a;
    return x.f.x + x.f.y;
}
__device__ __forceinline__ float sigf(float x) {
    return __fdividef(1.0f, 1.0f + __expf(-x));
}
__device__ __forceinline__ float tanf_(float x) {
    return __fdividef(2.0f, 1.0f + __expf(-2.0f * x)) - 1.0f;
}

// group barrier: 32 blocks sharing bt; monotone generation targets
__device__ __forceinline__ void gbar(unsigned* cnt, unsigned* gen, unsigned target) {
    __syncthreads();
    if (threadIdx.x == 0) {
        unsigned old;
        asm volatile("atom.add.acq_rel.gpu.global.u32 %0, [%1], 1;"
                     : "=r"(old) : "l"(cnt) : "memory");
        if (old == 31u) {
            asm volatile("st.relaxed.gpu.global.u32 [%0], %1;"
                         :: "l"(cnt), "r"(0u) : "memory");
            asm volatile("st.release.gpu.global.u32 [%0], %1;"
                         :: "l"(gen), "r"(target) : "memory");
        } else {
            unsigned v;
            do {
                asm volatile("ld.acquire.gpu.global.u32 %0, [%1];"
                             : "=r"(v) : "l"(gen) : "memory");
            } while (v < target);
        }
    }
    __syncthreads();
}

// ---------------- single fused persistent kernel ----------------
__global__ void __launch_bounds__(TPB, 1)
lstm_fused(const float* __restrict__ x,
           const float* __restrict__ Wgx, const float* __restrict__ Wgh, const float* __restrict__ bg,
           const float* __restrict__ Wix, const float* __restrict__ Wih, const float* __restrict__ bi,
           const float* __restrict__ Wfx, const float* __restrict__ Wfh, const float* __restrict__ bf,
           const float* __restrict__ Wox, const float* __restrict__ Woh, const float* __restrict__ bo,
           const float* __restrict__ Wph, const float* __restrict__ bp,
           float* __restrict__ out) {
    extern __shared__ float smem[];
    float* Ws  = smem;                        // [JT][4][GS]
    float* hs  = smem + JT * WJ;              // [BT][HS]
    float* red = smem + JT * WJ + BT * HS;    // [256][8]

    const int tid   = threadIdx.x;
    const int bt    = blockIdx.x >> 5;        // 0..3 (barrier group)
    const int jt    = blockIdx.x & 31;        // 0..31
    const int b0    = bt * BT;
    const int j0    = jt * JT;
    const int wid   = tid >> 5;               // 0..15
    const int lane  = tid & 31;
    const int kh    = wid >> 3;               // k-half (0/1)
    const int jp    = wid & 7;                // j-pair 0..7
    const int gpair = lane >> 4;              // 0:{g,i} 1:{f,o}
    const int bq    = lane & 15;
    const int bA    = b0 + bq;
    const int bB    = bA + 16;
    const int j_own = j0 + 2 * jp + gpair;

    unsigned* cnt = &g_cnt4[bt];
    unsigned* gen = &g_gen4[bt];

    // ---- phase 0a: transpose x slice (block covers t in [jt*32,jt*32+32), b slice) ----
#pragma unroll
    for (int i = 0; i < 2; i++) {
        int idx = tid + i * TPB;              // 0..1023
        int tt  = jt * 32 + (idx >> 5);
        int bb  = b0 + (idx & 31);
        g_xT[tt * B + bb] = x[(size_t)bb * T + tt];
    }

    // ---- phase 0b: gather W tile directly from the 4 recurrent matrices ----
#pragma unroll
    for (int g = 0; g < 4; g++) {
        const float* S = (g == 0) ? Wgh : (g == 1) ? Wih : (g == 2) ? Wfh : Woh;
#pragma unroll
        for (int i = 0; i < 16; i++) {
            int idx = tid + i * TPB;          // 0..8191
            int j16 = idx & 15;
            int k   = idx >> 4;               // 0..511
            Ws[j16 * WJ + g * GS + k] = S[k * H + j0 + j16];
        }
    }

    // per-thread input-projection weights / biases for j_own
    const float wxg = Wgx[j_own], wxi = Wix[j_own], wxf = Wfx[j_own], wxo = Wox[j_own];
    const float bvg = bg[j_own],  bvi = bi[j_own],  bvf = bf[j_own],  bvo = bo[j_own];

    const float* wbase = Ws + (2 * jp) * WJ + gpair * (2 * GS) + kh * 256;
    const float* hpA   = hs + bq * HS + kh * 256;
    const float* hpB   = hpA + 16 * HS;
    const int    pidx  = jp * 32 + lane;      // partner slot in red[]

    float cA = 0.f, cB = 0.f;

    gbar(cnt, gen, 1u);   // xT visible group-wide; Ws block-local done via the syncthreads inside

    for (int t = 0; t < T; t++) {
        float p[8];

        if (t > 0) {
            const float* hread = g_h[t & 1];
            // --- stage h[b0..b0+32) into padded smem rows ---
            {
                const float4* src = (const float4*)(hread + b0 * H);
#pragma unroll
                for (int i = 0; i < 8; i++) {             // 4096 f4 / 512 thr
                    int idx = tid + i * TPB;
                    int bb  = idx >> 7;
                    int q   = idx & 127;
                    float4 v = __ldcg(src + idx);
                    *(float4*)(hs + bb * HS + q * 4) = v;
                }
            }
            __syncthreads();

            // --- half-k GEMM: 2b x 2j x 2g tile, f32x2, LDS.128 ---
            ull acc[8];
#pragma unroll
            for (int i = 0; i < 8; i++) acc[i] = 0ull;
#pragma unroll 4
            for (int kq = 0; kq < 64; kq++) {
                const int ko = 4 * kq;
                ulonglong2 va = *(const ulonglong2*)(hpA + ko);
                ulonglong2 vb = *(const ulonglong2*)(hpB + ko);
#pragma unroll
                for (int jl = 0; jl < 2; jl++) {
#pragma unroll
                    for (int gl = 0; gl < 2; gl++) {
                        ulonglong2 w = *(const ulonglong2*)(wbase + jl * WJ + gl * GS + ko);
                        int ia = jl * 2 + gl;
                        acc[ia]     = fma2(va.x, w.x, acc[ia]);
                        acc[ia]     = fma2(va.y, w.y, acc[ia]);
                        acc[4 + ia] = fma2(vb.x, w.x, acc[4 + ia]);
                        acc[4 + ia] = fma2(vb.y, w.y, acc[4 + ia]);
                    }
                }
            }
#pragma unroll
            for (int i = 0; i < 8; i++) p[i] = hadd2(acc[i]);

            // --- combine k-halves through smem ---
            if (kh == 1) {
                *(float4*)(red + pidx * 8)     = make_float4(p[0], p[1], p[2], p[3]);
                *(float4*)(red + pidx * 8 + 4) = make_float4(p[4], p[5], p[6], p[7]);
            }
            __syncthreads();
            if (kh == 0) {
                float4 r0 = *(const float4*)(red + pidx * 8);
                float4 r1 = *(const float4*)(red + pidx * 8 + 4);
                p[0] += r0.x; p[1] += r0.y; p[2] += r0.z; p[3] += r0.w;
                p[4] += r1.x; p[5] += r1.y; p[6] += r1.z; p[7] += r1.w;
            }
        } else {
#pragma unroll
            for (int i = 0; i < 8; i++) p[i] = 0.f;
        }

        if (kh == 0) {
            // exchange other-j gate pair with partner half-warp lane
            const int jo = (1 - gpair) * 2;
            const int jm = gpair * 2;
            float rA0 = __shfl_xor_sync(0xffffffffu, p[jo + 0],     16);
            float rA1 = __shfl_xor_sync(0xffffffffu, p[jo + 1],     16);
            float rB0 = __shfl_xor_sync(0xffffffffu, p[4 + jo + 0], 16);
            float rB1 = __shfl_xor_sync(0xffffffffu, p[4 + jo + 1], 16);

            float gA = gpair ? rA0 : p[jm + 0];
            float iA = gpair ? rA1 : p[jm + 1];
            float fA = gpair ? p[jm + 0] : rA0;
            float oA = gpair ? p[jm + 1] : rA1;
            float gB = gpair ? rB0 : p[4 + jm + 0];
            float iB = gpair ? rB1 : p[4 + jm + 1];
            float fB = gpair ? p[4 + jm + 0] : rB0;
            float oB = gpair ? p[4 + jm + 1] : rB1;

            const float xA = __ldg(g_xT + t * B + bA);
            const float xB = __ldg(g_xT + t * B + bB);

            float gvA = tanf_(gA + xA * wxg + bvg);
            float ivA = sigf (iA + xA * wxi + bvi);
            float fvA = sigf (fA + xA * wxf + bvf);
            float ovA = sigf (oA + xA * wxo + bvo);
            cA = gvA * ivA + cA * fvA;
            float hAv = tanf_(cA) * ovA;

            float gvB = tanf_(gB + xB * wxg + bvg);
            float ivB = sigf (iB + xB * wxi + bvi);
            float fvB = sigf (fB + xB * wxf + bvf);
            float ovB = sigf (oB + xB * wxo + bvo);
            cB = gvB * ivB + cB * fvB;
            float hBv = tanf_(cB) * ovB;

            float* hwrite = g_h[(t + 1) & 1];
            hwrite[bA * H + j_own] = hAv;
            hwrite[bB * H + j_own] = hBv;
        }

        gbar(cnt, gen, (unsigned)(t + 2));
    }

    // ---- final projection: this block handles batch row b_out ----
    {
        const int b_out = b0 + jt;
        const float* hrow = g_h[0] + b_out * H;   // T even -> final state in buffer 0
        if (wid < NCLS) {
            const float* wr = Wph + wid * H;
            float s = 0.f;
#pragma unroll 4
            for (int j = lane; j < H; j += 32) s += hrow[j] * wr[j];
#pragma unroll
            for (int off = 16; off; off >>= 1) s += __shfl_down_sync(0xffffffffu, s, off);
            if (lane == 0) out[b_out * NCLS + wid] = s + bp[wid];
        }
    }

    // ---- reset group counters for the next graph replay ----
    __syncthreads();
    if (tid == 0) {
        unsigned old = atomicAdd(cnt, 1u);
        if (old == 31u) {
            asm volatile("st.relaxed.gpu.global.u32 [%0], %1;"
                         :: "l"(cnt), "r"(0u) : "memory");
            asm volatile("st.relaxed.gpu.global.u32 [%0], %1;"
                         :: "l"(gen), "r"(0u) : "memory");
        }
    }
}

// ---------------- launch ----------------
extern "C" void kernel_launch(void* const* d_in, const int* in_sizes, int n_in,
                              void* d_out, int out_size) {
    const float* x   = (const float*)d_in[0];
    const float* Wgx = (const float*)d_in[1];
    const float* Wgh = (const float*)d_in[2];
    const float* bg  = (const float*)d_in[3];
    const float* Wix = (const float*)d_in[4];
    const float* Wih = (const float*)d_in[5];
    const float* bi  = (const float*)d_in[6];
    const float* Wfx = (const float*)d_in[7];
    const float* Wfh = (const float*)d_in[8];
    const float* bf  = (const float*)d_in[9];
    const float* Wox = (const float*)d_in[10];
    const float* Woh = (const float*)d_in[11];
    const float* bo  = (const float*)d_in[12];
    const float* Wph = (const float*)d_in[13];
    const float* bp  = (const float*)d_in[14];
    float* out = (float*)d_out;

    cudaFuncSetAttribute(lstm_fused, cudaFuncAttributeMaxDynamicSharedMemorySize,
                         SMEM_BYTES);

    lstm_fused<<<GRID, TPB, SMEM_BYTES>>>(x,
        Wgx, Wgh, bg, Wix, Wih, bi, Wfx, Wfh, bf, Wox, Woh, bo, Wph, bp, out);
}